// round 15
// speedup vs baseline: 6.6912x; 1.0751x over previous
#include <cuda_runtime.h>
#include <cuda_fp16.h>
#include <math.h>
#include <stdint.h>

// ---------------------------------------------------------------------------
// Problem constants
// ---------------------------------------------------------------------------
namespace {
constexpr int Bz   = 2;
constexpr int Sq   = 2048;
constexpr int Dm   = 1024;
constexpr int Hn   = 16;
constexpr int HDm  = 64;
constexpr int FFNm = 2048;
constexpr int En   = 8;
constexpr int Tn   = Bz * Sq;     // 4096 tokens
constexpr int NA   = Tn * 2;      // 8192 flat assignments (top-2)
constexpr int CAPn = 1280;        // ceil(2*2048*2*1.25/8)
// prep_k region sizes (float4 units except rope)
constexpr int NQ4  = Dm * 3 * Dm / 4;        // 786432
constexpr int NO4  = Dm * Dm / 4;            // 262144
constexpr int NW14 = En * Dm * FFNm / 4;     // 4194304
constexpr int NW24 = En * FFNm * Dm / 4;     // 4194304
constexpr int NRP  = Sq * (HDm / 2);         // 65536
}

// ---------------------------------------------------------------------------
// Static scratch (no allocations allowed)
// ---------------------------------------------------------------------------
__device__ float g_x1  [Tn * Dm];
__device__ float g_cos [Sq * (HDm / 2)];
__device__ float g_sin [Sq * (HDm / 2)];
__device__ float g_fg  [NA];
__device__ int   g_fe  [NA];
__device__ int   g_slot[NA];
__device__ int   g_etok [En * CAPn];
__device__ float g_egate[En * CAPn];
__device__ int   g_cnt  [En];               // live rows per expert
__device__ float g_ye[En * CAPn * Dm];
// fp16 data
__device__ __half g_qh   [Tn * Dm];         // rope'd Q, pre-scaled 1/8
__device__ __half g_kh   [Tn * Dm];         // rope'd K
__device__ __half g_vh   [Tn * Dm];         // V
__device__ __half g_xnh  [Tn * Dm];         // rmsnorm1 out (qkv GEMM A)
__device__ __half g_xn2h [Tn * Dm];         // rmsnorm2 out (MoE gather src)
__device__ __half g_attnh[Tn * Dm];         // attention out (o GEMM A)
__device__ __half g_wqkvh[Dm * 3 * Dm];
__device__ __half g_woh  [Dm * Dm];
__device__ __half g_w1h  [En * Dm * FFNm];
__device__ __half g_w2h  [En * FFNm * Dm];
__device__ __half g_hh   [En * CAPn * FFNm];

// ---------------------------------------------------------------------------
// Helpers
// ---------------------------------------------------------------------------
__device__ __forceinline__ uint32_t smem_u32(const void* p) {
    uint32_t a;
    asm("{ .reg .u64 t; cvta.to.shared.u64 t, %1; cvt.u32.u64 %0, t; }"
        : "=r"(a) : "l"(p));
    return a;
}

__device__ __forceinline__ void cpasync16(uint32_t dst, const void* src) {
    asm volatile("cp.async.cg.shared.global [%0], [%1], 16;" :: "r"(dst), "l"(src));
}
// Zero-fill variant: src-size 0 -> smem dst gets zeros, no global read.
__device__ __forceinline__ void cpasync16z(uint32_t dst, const void* src, uint32_t ssz) {
    asm volatile("cp.async.cg.shared.global [%0], [%1], 16, %2;"
                 :: "r"(dst), "l"(src), "r"(ssz));
}
__device__ __forceinline__ void cp_commit() {
    asm volatile("cp.async.commit_group;" ::: "memory");
}
template <int N>
__device__ __forceinline__ void cp_wait() {
    asm volatile("cp.async.wait_group %0;" :: "n"(N) : "memory");
}

// fp16 m16n8k16 MMA, fp32 accumulate
__device__ __forceinline__ void mma_f16(float* d, const uint32_t* a, const uint32_t* b) {
    asm volatile(
        "mma.sync.aligned.m16n8k16.row.col.f32.f16.f16.f32 "
        "{%0,%1,%2,%3}, {%4,%5,%6,%7}, {%8,%9}, {%0,%1,%2,%3};"
        : "+f"(d[0]), "+f"(d[1]), "+f"(d[2]), "+f"(d[3])
        : "r"(a[0]), "r"(a[1]), "r"(a[2]), "r"(a[3]), "r"(b[0]), "r"(b[1]));
}

__device__ __forceinline__ void ldsm_x4(uint32_t* r, uint32_t addr) {
    asm volatile("ldmatrix.sync.aligned.m8n8.x4.shared.b16 {%0,%1,%2,%3}, [%4];"
                 : "=r"(r[0]), "=r"(r[1]), "=r"(r[2]), "=r"(r[3]) : "r"(addr));
}
__device__ __forceinline__ void ldsm_x4_t(uint32_t* r, uint32_t addr) {
    asm volatile("ldmatrix.sync.aligned.m8n8.x4.trans.shared.b16 {%0,%1,%2,%3}, [%4];"
                 : "=r"(r[0]), "=r"(r[1]), "=r"(r[2]), "=r"(r[3]) : "r"(addr));
}

// 2^x for x <= 0, FMA-pipe only.
__device__ __forceinline__ float exp2p(float x) {
    float t = fmaxf(x, -126.f);
    float z = t + 12582912.f;
    float n = z - 12582912.f;
    float f = t - n;
    float p =         1.5353e-4f;
    p = fmaf(p, f, 1.3398886e-3f);
    p = fmaf(p, f, 9.6184372e-3f);
    p = fmaf(p, f, 5.5503327e-2f);
    p = fmaf(p, f, 2.4022648e-1f);
    p = fmaf(p, f, 6.9314718e-1f);
    p = fmaf(p, f, 1.0f);
    int iz = __float_as_int(z) - 0x4B400000;
    return p * __int_as_float((iz + 127) << 23);
}

__device__ __forceinline__ uint32_t h2_bits(float a, float b) {
    __half2 h = __float22half2_rn(make_float2(a, b));
    return *(uint32_t*)&h;
}

// ---------------------------------------------------------------------------
// Fused prep: fp16-convert all four weight tensors + rope table. One launch.
// ---------------------------------------------------------------------------
__global__ void prep_k(const float* __restrict__ wqkv, __half* __restrict__ wqkvh,
                       const float* __restrict__ wo,   __half* __restrict__ woh,
                       const float* __restrict__ w1,   __half* __restrict__ w1h,
                       const float* __restrict__ w2,   __half* __restrict__ w2h,
                       float* __restrict__ ct, float* __restrict__ st) {
    const int total = NQ4 + NO4 + NW14 + NW24 + NRP;
    int stride = gridDim.x * blockDim.x;
    for (int i = blockIdx.x * blockDim.x + threadIdx.x; i < total; i += stride) {
        int r = i;
        if (r < NQ4) {
            float4 v = ((const float4*)wqkv)[r];
            ((uint2*)wqkvh)[r] = make_uint2(h2_bits(v.x, v.y), h2_bits(v.z, v.w));
            continue;
        }
        r -= NQ4;
        if (r < NO4) {
            float4 v = ((const float4*)wo)[r];
            ((uint2*)woh)[r] = make_uint2(h2_bits(v.x, v.y), h2_bits(v.z, v.w));
            continue;
        }
        r -= NO4;
        if (r < NW14) {
            float4 v = ((const float4*)w1)[r];
            ((uint2*)w1h)[r] = make_uint2(h2_bits(v.x, v.y), h2_bits(v.z, v.w));
            continue;
        }
        r -= NW14;
        if (r < NW24) {
            float4 v = ((const float4*)w2)[r];
            ((uint2*)w2h)[r] = make_uint2(h2_bits(v.x, v.y), h2_bits(v.z, v.w));
            continue;
        }
        r -= NW24;
        {
            int s = r >> 5, j = r & 31;
            float th = (float)pow(10000.0, -2.0 * (double)j / (double)HDm);
            double f = (double)s * (double)th;
            ct[r] = (float)cos(f);
            st[r] = (float)sin(f);
        }
    }
}

// ---------------------------------------------------------------------------
// RMSNorm (fp16 out; feeds qkv GEMM)
// ---------------------------------------------------------------------------
__global__ void __launch_bounds__(256) rmsnorm_k(const float* __restrict__ x,
                                                 const float* __restrict__ g,
                                                 __half* __restrict__ y) {
    int row = blockIdx.x;
    int i = threadIdx.x;
    const float4* xr = (const float4*)(x + (size_t)row * Dm);
    float4 xv = xr[i];
    float ss = xv.x * xv.x + xv.y * xv.y + xv.z * xv.z + xv.w * xv.w;
#pragma unroll
    for (int off = 16; off; off >>= 1) ss += __shfl_down_sync(0xffffffffu, ss, off);
    __shared__ float red[8];
    __shared__ float srms;
    if ((i & 31) == 0) red[i >> 5] = ss;
    __syncthreads();
    if (i == 0) {
        float t = 0.f;
#pragma unroll
        for (int w = 0; w < 8; w++) t += red[w];
        srms = rsqrtf(t * (1.0f / Dm) + 1e-6f);
    }
    __syncthreads();
    float r = srms;
    float4 gv = ((const float4*)g)[i];
    ((uint2*)(y + (size_t)row * Dm))[i] =
        make_uint2(h2_bits(gv.x * xv.x * r, gv.y * xv.y * r),
                   h2_bits(gv.z * xv.z * r, gv.w * xv.w * r));
}

// ---------------------------------------------------------------------------
// Fused RMSNorm2 + router: norm -> xn (fp16, MoE gather source), 8 logits,
// softmax, top-2. One block per token.
// ---------------------------------------------------------------------------
__global__ void __launch_bounds__(256) rmsrouter_k(const float* __restrict__ x,
                                                   const float* __restrict__ g,
                                                   const float* __restrict__ wr,
                                                   __half* __restrict__ xnh,
                                                   float* __restrict__ fg,
                                                   int* __restrict__ fe,
                                                   int* __restrict__ cnt) {
    int row = blockIdx.x;
    int i = threadIdx.x;
    if (row == 0 && i < En) cnt[i] = 0;
    const float4* xr = (const float4*)(x + (size_t)row * Dm);
    float4 xv = xr[i];
    float ss = xv.x * xv.x + xv.y * xv.y + xv.z * xv.z + xv.w * xv.w;
#pragma unroll
    for (int off = 16; off; off >>= 1) ss += __shfl_down_sync(0xffffffffu, ss, off);
    __shared__ float red[8];
    __shared__ float srms;
    if ((i & 31) == 0) red[i >> 5] = ss;
    __syncthreads();
    if (i == 0) {
        float t = 0.f;
#pragma unroll
        for (int w = 0; w < 8; w++) t += red[w];
        srms = rsqrtf(t * (1.0f / Dm) + 1e-6f);
    }
    __syncthreads();
    float r = srms;
    float4 gv = ((const float4*)g)[i];
    float o[4];
    o[0] = gv.x * xv.x * r; o[1] = gv.y * xv.y * r;
    o[2] = gv.z * xv.z * r; o[3] = gv.w * xv.w * r;
    ((uint2*)(xnh + (size_t)row * Dm))[i] =
        make_uint2(h2_bits(o[0], o[1]), h2_bits(o[2], o[3]));

    float acc[8];
#pragma unroll
    for (int e = 0; e < 8; e++) acc[e] = 0.f;
#pragma unroll
    for (int c = 0; c < 4; c++) {
        const float4* w = (const float4*)(wr + (size_t)(4 * i + c) * En);
        float4 w0 = w[0], w1 = w[1];
        acc[0] = fmaf(o[c], w0.x, acc[0]); acc[1] = fmaf(o[c], w0.y, acc[1]);
        acc[2] = fmaf(o[c], w0.z, acc[2]); acc[3] = fmaf(o[c], w0.w, acc[3]);
        acc[4] = fmaf(o[c], w1.x, acc[4]); acc[5] = fmaf(o[c], w1.y, acc[5]);
        acc[6] = fmaf(o[c], w1.z, acc[6]); acc[7] = fmaf(o[c], w1.w, acc[7]);
    }
#pragma unroll
    for (int e = 0; e < 8; e++)
#pragma unroll
        for (int off = 16; off; off >>= 1)
            acc[e] += __shfl_down_sync(0xffffffffu, acc[e], off);
    __shared__ float lred[8][8];
    if ((i & 31) == 0)
#pragma unroll
        for (int e = 0; e < 8; e++) lred[i >> 5][e] = acc[e];
    __syncthreads();
    if (i == 0) {
        float p[8];
#pragma unroll
        for (int e = 0; e < 8; e++) {
            float s = 0.f;
#pragma unroll
            for (int w = 0; w < 8; w++) s += lred[w][e];
            p[e] = s;
        }
        float mx = p[0];
#pragma unroll
        for (int e = 1; e < 8; e++) mx = fmaxf(mx, p[e]);
        float sum = 0.f;
#pragma unroll
        for (int e = 0; e < 8; e++) { p[e] = expf(p[e] - mx); sum += p[e]; }
        float inv = 1.f / sum;
#pragma unroll
        for (int e = 0; e < 8; e++) p[e] *= inv;
        int e0 = 0; float p0 = p[0];
#pragma unroll
        for (int e = 1; e < 8; e++) if (p[e] > p0) { p0 = p[e]; e0 = e; }
        int e1 = -1; float p1 = -1.f;
#pragma unroll
        for (int e = 0; e < 8; e++)
            if (e != e0 && p[e] > p1) { p1 = p[e]; e1 = e; }
        fg[2 * row]     = p0; fe[2 * row]     = e0;
        fg[2 * row + 1] = p1; fe[2 * row + 1] = e1;
    }
}

// ---------------------------------------------------------------------------
// Tensor-core causal flash attention, all-fp16 MMAs.
// launch_bounds(256,2): cap 128 regs -> 2 CTAs/SM (was 136 regs, 1 CTA/SM,
// occ 12.5%, latency-bound per ncu). blockIdx.x reversed so the heavy
// diagonal CTAs (work ~ 2bx+2) schedule first (triangular-load packing).
// ---------------------------------------------------------------------------
__global__ void __launch_bounds__(256, 2) attn_tc_k(const __half* __restrict__ Q,
                                                    const __half* __restrict__ Kt,
                                                    const __half* __restrict__ Vt,
                                                    __half* __restrict__ Out) {
    extern __shared__ __align__(16) char smc[];
    constexpr float LOG2E = 1.4426950408889634f;
    constexpr int KBYTES = 64 * 144;            // 9216
    constexpr int STGB = KBYTES + 64 * 128;     // + V 8192 = 17408

    int bx = gridDim.x - 1 - blockIdx.x;        // heavy tiles first
    int h = blockIdx.y, b = blockIdx.z;
    int qt = bx * 128;
    int tid = threadIdx.x, warp = tid >> 5, lane = tid & 31;
    int gq = lane >> 2, tq = lane & 3;
    int wq = qt + warp * 16;
    const size_t base = ((size_t)(b * Hn + h)) * Sq * HDm;
    const __half* Qg = Q + base;
    const __half* Kg = Kt + base;
    const __half* Vg = Vt + base;

    const uint32_t sb = smem_u32(smc);

    uint32_t qf[4][4];
#pragma unroll
    for (int kk = 0; kk < 4; kk++) {
        const __half* q0 = Qg + (size_t)(wq + gq) * 64 + kk * 16 + 2 * tq;
        const __half* q1 = Qg + (size_t)(wq + gq + 8) * 64 + kk * 16 + 2 * tq;
        qf[kk][0] = *(const uint32_t*)q0;
        qf[kk][1] = *(const uint32_t*)q1;
        qf[kk][2] = *(const uint32_t*)(q0 + 8);
        qf[kk][3] = *(const uint32_t*)(q1 + 8);
    }

    float O[8][4];
#pragma unroll
    for (int nt = 0; nt < 8; nt++)
#pragma unroll
        for (int c = 0; c < 4; c++) O[nt][c] = 0.f;
    float m0 = -1e30f, m1 = -1e30f, l0 = 0.f, l1 = 0.f;

    int fr = tid >> 2;
    int fc = tid & 3;
    auto fill = [&](int stage, int kt) {
        uint32_t kDst = sb + (uint32_t)(stage * STGB + fr * 144 + fc * 32);
        const __half* ks = Kg + (size_t)(kt + fr) * 64 + fc * 16;
        cpasync16(kDst, ks);
        cpasync16(kDst + 16u, ks + 8);
        uint32_t vBase = sb + (uint32_t)(stage * STGB + KBYTES + fr * 128);
        const __half* vs = Vg + (size_t)(kt + fr) * 64;
        uint32_t sw = (uint32_t)(fr & 7);
#pragma unroll
        for (int j = 0; j < 2; j++) {
            uint32_t c = (uint32_t)(fc * 2 + j);
            cpasync16(vBase + ((c ^ sw) * 16u), vs + c * 8);
        }
    };

    int ntiles = 2 * bx + 2;
    fill(0, 0);
    cp_commit();

    int lrow = lane & 7, selb = (lane >> 3) & 1, selc = lane >> 4;

    for (int it = 0; it < ntiles; it++) {
        if (it + 1 < ntiles) fill((it + 1) & 1, (it + 1) * 64);
        cp_commit();
        cp_wait<1>();
        __syncthreads();

        int kt = it * 64;
        if (kt <= wq + 15) {
            const __half* Ks = (const __half*)(smc + (it & 1) * STGB);
            const uint32_t Vsb = sb + (uint32_t)((it & 1) * STGB + KBYTES);

            float s[8][4];
#pragma unroll
            for (int nt = 0; nt < 8; nt++)
#pragma unroll
                for (int c = 0; c < 4; c++) s[nt][c] = 0.f;
#pragma unroll
            for (int kk = 0; kk < 4; kk++) {
                uint32_t bf[8][2];
#pragma unroll
                for (int nt = 0; nt < 8; nt++) {
                    const __half* kr = Ks + (nt * 8 + gq) * 72 + kk * 16 + 2 * tq;
                    bf[nt][0] = *(const uint32_t*)kr;
                    bf[nt][1] = *(const uint32_t*)(kr + 8);
                }
#pragma unroll
                for (int nt = 0; nt < 8; nt++) mma_f16(s[nt], qf[kk], bf[nt]);
            }

            if (kt + 63 > wq) {
                int r0 = wq + gq, r1 = wq + gq + 8;
#pragma unroll
                for (int nt = 0; nt < 8; nt++) {
                    int c0 = kt + nt * 8 + 2 * tq;
                    if (c0 > r0)     s[nt][0] = -3.4e38f;
                    if (c0 + 1 > r0) s[nt][1] = -3.4e38f;
                    if (c0 > r1)     s[nt][2] = -3.4e38f;
                    if (c0 + 1 > r1) s[nt][3] = -3.4e38f;
                }
            }

            float mx0 = -3.4e38f, mx1 = -3.4e38f;
#pragma unroll
            for (int nt = 0; nt < 8; nt++) {
                mx0 = fmaxf(mx0, fmaxf(s[nt][0], s[nt][1]));
                mx1 = fmaxf(mx1, fmaxf(s[nt][2], s[nt][3]));
            }
            mx0 = fmaxf(mx0, __shfl_xor_sync(0xffffffffu, mx0, 1));
            mx0 = fmaxf(mx0, __shfl_xor_sync(0xffffffffu, mx0, 2));
            mx1 = fmaxf(mx1, __shfl_xor_sync(0xffffffffu, mx1, 1));
            mx1 = fmaxf(mx1, __shfl_xor_sync(0xffffffffu, mx1, 2));
            float mn0 = fmaxf(m0, mx0), mn1 = fmaxf(m1, mx1);
            float cr0 = exp2p((m0 - mn0) * LOG2E);
            float cr1 = exp2p((m1 - mn1) * LOG2E);
            float nm0 = mn0 * LOG2E, nm1 = mn1 * LOG2E;

            float sum0 = 0.f, sum1 = 0.f;
#pragma unroll
            for (int nt = 0; nt < 8; nt++) {
                float p0 = exp2p(fmaf(s[nt][0], LOG2E, -nm0));
                float p1 = exp2p(fmaf(s[nt][1], LOG2E, -nm0));
                float p2 = exp2p(fmaf(s[nt][2], LOG2E, -nm1));
                float p3 = exp2p(fmaf(s[nt][3], LOG2E, -nm1));
                s[nt][0] = p0; s[nt][1] = p1; s[nt][2] = p2; s[nt][3] = p3;
                sum0 += p0 + p1; sum1 += p2 + p3;
            }
            sum0 += __shfl_xor_sync(0xffffffffu, sum0, 1);
            sum0 += __shfl_xor_sync(0xffffffffu, sum0, 2);
            sum1 += __shfl_xor_sync(0xffffffffu, sum1, 1);
            sum1 += __shfl_xor_sync(0xffffffffu, sum1, 2);
            l0 = l0 * cr0 + sum0;
            l1 = l1 * cr1 + sum1;
#pragma unroll
            for (int nt = 0; nt < 8; nt++) {
                O[nt][0] *= cr0; O[nt][1] *= cr0;
                O[nt][2] *= cr1; O[nt][3] *= cr1;
            }
            m0 = mn0; m1 = mn1;

#pragma unroll
            for (int kk = 0; kk < 4; kk++) {
                uint32_t a[4];
                a[0] = h2_bits(s[2 * kk][0],     s[2 * kk][1]);
                a[1] = h2_bits(s[2 * kk][2],     s[2 * kk][3]);
                a[2] = h2_bits(s[2 * kk + 1][0], s[2 * kk + 1][1]);
                a[3] = h2_bits(s[2 * kk + 1][2], s[2 * kk + 1][3]);
                uint32_t bvv[8][2];
#pragma unroll
                for (int np = 0; np < 4; np++) {
                    uint32_t qd[4];
                    uint32_t addr = Vsb + (uint32_t)((lrow + 8 * selb) * 128)
                                  + (uint32_t)(kk * 2048)
                                  + ((((uint32_t)(selc + 2 * np)) ^ (uint32_t)lrow) * 16u);
                    ldsm_x4_t(qd, addr);
                    bvv[2 * np][0]     = qd[0]; bvv[2 * np][1]     = qd[1];
                    bvv[2 * np + 1][0] = qd[2]; bvv[2 * np + 1][1] = qd[3];
                }
#pragma unroll
                for (int nt = 0; nt < 8; nt++) mma_f16(O[nt], a, bvv[nt]);
            }
        }
        __syncthreads();
    }

    float i0 = 1.f / l0, i1 = 1.f / l1;
    int r0 = wq + gq, r1 = wq + gq + 8;
    __half* o0 = Out + ((size_t)(b * Sq + r0)) * Dm + h * 64 + 2 * tq;
    __half* o1 = Out + ((size_t)(b * Sq + r1)) * Dm + h * 64 + 2 * tq;
#pragma unroll
    for (int nt = 0; nt < 8; nt++) {
        *(uint32_t*)(o0 + nt * 8) = h2_bits(O[nt][0] * i0, O[nt][1] * i0);
        *(uint32_t*)(o1 + nt * 8) = h2_bits(O[nt][2] * i1, O[nt][3] * i1);
    }
}

// ---------------------------------------------------------------------------
// fp16 tensor-core GEMM: CTA 128xNT, 8 warps, BK=32, 4-stage cp.async,
// ldmatrix, m16n8k16.f16, ONE barrier/iter. NT=128 kernels run 2 CTAs/SM.
// MODE 0: C(f32)=A@B            1: +resid
// MODE 2: C(f16)=relu(A@B)      3: C(f32)=(A@B)*gates[row]
// MODE 4: rope+split epilogue -> q(x1/8)/k/v fp16 (qkv projection)
// SKIP: early-exit CTAs past cnt[e]. GATHER: A rows via etok (zero-fill dead).
// ---------------------------------------------------------------------------
template <int MODE, bool SKIP, bool GATHER, int NT>
__global__ void __launch_bounds__(256, (NT == 128) ? 2 : 1)
gemm_h_k(const __half* __restrict__ A, const __half* __restrict__ Bm,
         void* __restrict__ Cp, int N, int K,
         const float* __restrict__ extra, const int* __restrict__ cnt,
         const int* __restrict__ etok,
         const float* __restrict__ ct, const float* __restrict__ st,
         __half* __restrict__ kOut, __half* __restrict__ vOut,
         long sA, long sB, long sC, int gstride) {
    extern __shared__ __align__(16) float smf[];
    const uint32_t sb = smem_u32(smf);
    constexpr int NTW  = NT / 32;
    constexpr int CPT  = NT / 64;
    constexpr uint32_t BROW = NT * 2;
    constexpr uint32_t STGB = 8192u + 32u * BROW;

    int e = blockIdx.z;
    int m0 = blockIdx.y * 128, n0 = blockIdx.x * NT;
    int cntE = 0;
    if (SKIP) {
        cntE = cnt[e];
        if (m0 >= cntE) return;
    }

    int tid = threadIdx.x, warp = tid >> 5, lane = tid & 31;
    int gq = lane >> 2, tq = lane & 3;
    if (!GATHER) A += (size_t)e * sA;
    Bm += (size_t)e * sB;
    const float* gates = extra;
    if (MODE == 3) gates += (size_t)e * gstride;

    int wm = (warp & 1) * 64, wn = (warp >> 1) * (NT / 4);

    int ar = tid >> 1, ah = tid & 1;
    int br2 = tid >> 3, bc0 = (tid & 7) * CPT;
    const __half* aSrc;
    uint32_t aLive = 16u;
    if (GATHER) {
        int rr = m0 + ar;
        bool live = rr < cntE;
        int tok = live ? etok[e * CAPn + rr] : 0;
        aLive = live ? 16u : 0u;
        aSrc = A + (size_t)tok * K + ah * 16;
    } else {
        aSrc = A + (size_t)(m0 + ar) * K + ah * 16;
    }
    const __half* bSrc = Bm + (size_t)br2 * N + n0 + bc0 * 8;
    uint32_t aS = (ar >> 1) & 3;
    uint32_t aBase = sb + (uint32_t)ar * 64u;
    uint32_t bBase = sb + 8192u + (uint32_t)br2 * BROW;

    auto fetch = [&](int stage, int k0) {
        uint32_t so = (uint32_t)stage * STGB;
        const __half* as = aSrc + k0;
        uint32_t c0 = 2u * ah;
        if (GATHER) {
            cpasync16z(aBase + so + ((c0 ^ aS) * 16u), as, aLive);
            cpasync16z(aBase + so + (((c0 + 1) ^ aS) * 16u), as + 8, aLive);
        } else {
            cpasync16(aBase + so + ((c0 ^ aS) * 16u), as);
            cpasync16(aBase + so + (((c0 + 1) ^ aS) * 16u), as + 8);
        }
        const __half* bs = bSrc + (size_t)k0 * N;
#pragma unroll
        for (int j = 0; j < CPT; j++) {
            uint32_t c = (uint32_t)(bc0 + j);
            cpasync16(bBase + so + ((c ^ (uint32_t)(br2 & 7)) * 16u), bs + j * 8);
        }
    };

    float d[4][NTW][4];
#pragma unroll
    for (int i = 0; i < 4; i++)
#pragma unroll
        for (int j = 0; j < NTW; j++)
#pragma unroll
            for (int c = 0; c < 4; c++) d[i][j][c] = 0.f;

    fetch(0, 0);  cp_commit();
    fetch(1, 32); cp_commit();
    fetch(2, 64); cp_commit();

    int lrow = lane & 7, selb = (lane >> 3) & 1, selc = lane >> 4;
    uint32_t aRow = (uint32_t)(wm + lrow + 8 * selb) * 64u;
    uint32_t aSw  = (uint32_t)((lrow >> 1) & 3);
    uint32_t bRow = (uint32_t)(lrow + 8 * selb) * BROW;
    uint32_t bCb  = (uint32_t)((wn >> 3) + selc);

    int KB = K >> 5;
    for (int it = 0; it < KB; ++it) {
        cp_wait<2>();
        __syncthreads();
        if (it + 3 < KB) fetch((it + 3) & 3, (it + 3) * 32);
        cp_commit();

        uint32_t As = sb + (uint32_t)(it & 3) * STGB;
        uint32_t Bs = As + 8192u;
#pragma unroll
        for (int kk = 0; kk < 2; kk++) {
            uint32_t a[4][4], b[NTW][2];
#pragma unroll
            for (int mt = 0; mt < 4; mt++) {
                uint32_t addr = As + aRow + (uint32_t)mt * 1024u
                              + ((((uint32_t)(2 * kk) + (uint32_t)selc) ^ aSw) * 16u);
                ldsm_x4(a[mt], addr);
            }
#pragma unroll
            for (int np = 0; np < NTW / 2; np++) {
                uint32_t q[4];
                uint32_t addr = Bs + bRow + (uint32_t)kk * 16u * BROW
                              + (((bCb + 2u * np) ^ (uint32_t)lrow) * 16u);
                ldsm_x4_t(q, addr);
                b[2 * np][0]     = q[0]; b[2 * np][1]     = q[1];
                b[2 * np + 1][0] = q[2]; b[2 * np + 1][1] = q[3];
            }
#pragma unroll
            for (int mt = 0; mt < 4; mt++)
#pragma unroll
                for (int nt = 0; nt < NTW; nt++)
                    mma_f16(d[mt][nt], a[mt], b[nt]);
        }
    }

    if (MODE == 4) {
        int region = n0 >> 10;
        __half* q0v[3] = { (__half*)Cp, kOut, vOut };
        __half* outb = q0v[region];
#pragma unroll
        for (int mt = 0; mt < 4; mt++) {
#pragma unroll
            for (int half = 0; half < 2; half++) {
                int row = m0 + wm + mt * 16 + gq + 8 * half;
                int bb = row >> 11, s = row & (Sq - 1);
                float va = 0.f, vb = 0.f;
#pragma unroll
                for (int nt = 0; nt < NTW; nt++) {
                    int c = n0 + wn + nt * 8 + 2 * tq;
                    va = d[mt][nt][2 * half];
                    vb = d[mt][nt][2 * half + 1];
                    int cc = c & 1023;
                    int hh = cc >> 6, dd = cc & 63;
                    size_t off = ((size_t)(bb * Hn + hh) * Sq + s) * HDm + dd;
                    uint32_t bits;
                    if (region == 2) {
                        bits = h2_bits(va, vb);
                    } else {
                        int j = dd >> 1;
                        float cs = ct[s * 32 + j], sn = st[s * 32 + j];
                        float orr = va * cs - vb * sn;
                        float oii = va * sn + vb * cs;
                        if (region == 0) { orr *= 0.125f; oii *= 0.125f; }
                        bits = h2_bits(orr, oii);
                    }
                    *(uint32_t*)(outb + off) = bits;
                }
            }
        }
        return;
    }

#pragma unroll
    for (int mt = 0; mt < 4; mt++) {
        int r0 = m0 + wm + mt * 16 + gq;
        int r1 = r0 + 8;
        if (MODE == 2) {
            __half* Cb = (__half*)Cp + (size_t)e * sC;
#pragma unroll
            for (int nt = 0; nt < NTW; nt++) {
                int c = n0 + wn + nt * 8 + 2 * tq;
                *(uint32_t*)(Cb + (size_t)r0 * N + c) =
                    h2_bits(fmaxf(d[mt][nt][0], 0.f), fmaxf(d[mt][nt][1], 0.f));
                *(uint32_t*)(Cb + (size_t)r1 * N + c) =
                    h2_bits(fmaxf(d[mt][nt][2], 0.f), fmaxf(d[mt][nt][3], 0.f));
            }
        } else if (MODE != 4) {
            float* Cf = (float*)Cp + (size_t)e * sC;
            float g0 = 1.f, g1 = 1.f;
            if (MODE == 3) { g0 = gates[r0]; g1 = gates[r1]; }
#pragma unroll
            for (int nt = 0; nt < NTW; nt++) {
                int c = n0 + wn + nt * 8 + 2 * tq;
                float2 u, w;
                u.x = d[mt][nt][0]; u.y = d[mt][nt][1];
                w.x = d[mt][nt][2]; w.y = d[mt][nt][3];
                if (MODE == 1) {
                    float2 ra = *(const float2*)(extra + (size_t)r0 * N + c);
                    float2 rb = *(const float2*)(extra + (size_t)r1 * N + c);
                    u.x += ra.x; u.y += ra.y;
                    w.x += rb.x; w.y += rb.y;
                }
                if (MODE == 3) {
                    u.x *= g0; u.y *= g0;
                    w.x *= g1; w.y *= g1;
                }
                *(float2*)(Cf + (size_t)r0 * N + c) = u;
                *(float2*)(Cf + (size_t)r1 * N + c) = w;
            }
        }
    }
}

// ---------------------------------------------------------------------------
// Exact capacity ranking.
// ---------------------------------------------------------------------------
__global__ void __launch_bounds__(256) rank_k(const float* __restrict__ fg,
                                              const int* __restrict__ fe,
                                              int* __restrict__ slot,
                                              int* __restrict__ etok,
                                              float* __restrict__ egate,
                                              int* __restrict__ cnt) {
    __shared__ float sg[NA];
    __shared__ unsigned char se[NA];
    for (int i = threadIdx.x; i < NA; i += 256) {
        sg[i] = fg[i];
        se[i] = (unsigned char)fe[i];
    }
    __syncthreads();
    int i = blockIdx.x * 256 + threadIdx.x;
    float gi = sg[i];
    unsigned char ei = se[i];
    int r = 0;
    for (int j = 0; j < NA; j++) {
        bool c = (se[j] == ei) && ((sg[j] > gi) || (sg[j] == gi && j < i));
        r += (int)c;
    }
    if (r < CAPn) {
        slot[i] = r;
        etok[(int)ei * CAPn + r] = i >> 1;
        egate[(int)ei * CAPn + r] = gi;
        atomicMax(&cnt[(int)ei], r + 1);
    } else {
        slot[i] = -1;
    }
}

// ---------------------------------------------------------------------------
// Final combine
// ---------------------------------------------------------------------------
__global__ void __launch_bounds__(256) combine_k(const float* __restrict__ x1,
                                                 const float* __restrict__ ye,
                                                 const int* __restrict__ fe,
                                                 const int* __restrict__ slot,
                                                 float* __restrict__ out) {
    int t = blockIdx.x;
    int d = threadIdx.x;
    float4 v = ((const float4*)(x1 + (size_t)t * Dm))[d];
#pragma unroll
    for (int kk = 0; kk < 2; kk++) {
        int i = 2 * t + kk;
        int sl = slot[i];
        if (sl >= 0) {
            int e = fe[i];
            float4 w = ((const float4*)(ye + ((size_t)e * CAPn + sl) * Dm))[d];
            v.x += w.x; v.y += w.y; v.z += w.z; v.w += w.w;
        }
    }
    ((float4*)(out + (size_t)t * Dm))[d] = v;
}

// ---------------------------------------------------------------------------
// Launch (single stream)
// ---------------------------------------------------------------------------
extern "C" void kernel_launch(void* const* d_in, const int* in_sizes, int n_in,
                              void* d_out, int out_size) {
    (void)in_sizes; (void)n_in; (void)out_size;
    const float* x        = (const float*)d_in[0];
    const float* g1       = (const float*)d_in[1];
    const float* w_qkv    = (const float*)d_in[2];
    const float* w_o      = (const float*)d_in[3];
    const float* g2       = (const float*)d_in[4];
    const float* w_router = (const float*)d_in[5];
    const float* w1       = (const float*)d_in[6];
    const float* w2       = (const float*)d_in[7];
    float* out = (float*)d_out;

    float *p_x1, *p_cos, *p_sin, *p_fg, *p_egate, *p_ye;
    __half *p_qh, *p_kh, *p_vh, *p_xnh, *p_xn2h, *p_attnh;
    __half *p_wqkvh, *p_woh, *p_w1h, *p_w2h, *p_hh;
    int *p_fe, *p_slot, *p_etok, *p_cnt;
    cudaGetSymbolAddress((void**)&p_x1,    g_x1);
    cudaGetSymbolAddress((void**)&p_cos,   g_cos);
    cudaGetSymbolAddress((void**)&p_sin,   g_sin);
    cudaGetSymbolAddress((void**)&p_fg,    g_fg);
    cudaGetSymbolAddress((void**)&p_fe,    g_fe);
    cudaGetSymbolAddress((void**)&p_slot,  g_slot);
    cudaGetSymbolAddress((void**)&p_etok,  g_etok);
    cudaGetSymbolAddress((void**)&p_egate, g_egate);
    cudaGetSymbolAddress((void**)&p_cnt,   g_cnt);
    cudaGetSymbolAddress((void**)&p_ye,    g_ye);
    cudaGetSymbolAddress((void**)&p_qh,    g_qh);
    cudaGetSymbolAddress((void**)&p_kh,    g_kh);
    cudaGetSymbolAddress((void**)&p_vh,    g_vh);
    cudaGetSymbolAddress((void**)&p_xnh,   g_xnh);
    cudaGetSymbolAddress((void**)&p_xn2h,  g_xn2h);
    cudaGetSymbolAddress((void**)&p_attnh, g_attnh);
    cudaGetSymbolAddress((void**)&p_wqkvh, g_wqkvh);
    cudaGetSymbolAddress((void**)&p_woh,   g_woh);
    cudaGetSymbolAddress((void**)&p_w1h,   g_w1h);
    cudaGetSymbolAddress((void**)&p_w2h,   g_w2h);
    cudaGetSymbolAddress((void**)&p_hh,    g_hh);

    constexpr int H_SMEM256 = 4 * 24576;        // 98304 bytes
    constexpr int H_SMEM128 = 4 * 16384;        // 65536 bytes
    constexpr int ATTN_SMEM = 2 * 17408;        // 34816 bytes
    cudaFuncSetAttribute((const void*)gemm_h_k<4, false, false, 256>,
                         cudaFuncAttributeMaxDynamicSharedMemorySize, H_SMEM256);
    cudaFuncSetAttribute((const void*)gemm_h_k<1, false, false, 256>,
                         cudaFuncAttributeMaxDynamicSharedMemorySize, H_SMEM256);
    cudaFuncSetAttribute((const void*)gemm_h_k<2, true, true, 128>,
                         cudaFuncAttributeMaxDynamicSharedMemorySize, H_SMEM128);
    cudaFuncSetAttribute((const void*)gemm_h_k<3, true, false, 128>,
                         cudaFuncAttributeMaxDynamicSharedMemorySize, H_SMEM128);
    cudaFuncSetAttribute((const void*)attn_tc_k,
                         cudaFuncAttributeMaxDynamicSharedMemorySize, ATTN_SMEM);

    // Fused precompute: fp16 weight conversions + rope table in ONE launch
    prep_k<<<1184, 256>>>(w_qkv, p_wqkvh, w_o, p_woh,
                          w1, p_w1h, w2, p_w2h, p_cos, p_sin);

    // Attention branch: qkv GEMM with fused rope/split epilogue
    rmsnorm_k<<<Tn, 256>>>(x, g1, p_xnh);
    gemm_h_k<4, false, false, 256><<<dim3(3 * Dm / 256, Tn / 128, 1), 256, H_SMEM256>>>(
        p_xnh, p_wqkvh, p_qh, 3 * Dm, Dm, nullptr, nullptr, nullptr,
        p_cos, p_sin, p_kh, p_vh, 0, 0, 0, 0);
    attn_tc_k<<<dim3(Sq / 128, Hn, Bz), 256, ATTN_SMEM>>>(p_qh, p_kh, p_vh, p_attnh);
    gemm_h_k<1, false, false, 256><<<dim3(Dm / 256, Tn / 128, 1), 256, H_SMEM256>>>(
        p_attnh, p_woh, p_x1, Dm, Dm, x, nullptr, nullptr,
        nullptr, nullptr, nullptr, nullptr, 0, 0, 0, 0);

    // Fused rmsnorm2 + routing (fp32 exact; xn emitted fp16 for MoE gather)
    rmsrouter_k<<<Tn, 256>>>(p_x1, g2, w_router, p_xn2h, p_fg, p_fe, p_cnt);
    rank_k<<<NA / 256, 256>>>(p_fg, p_fe, p_slot, p_etok, p_egate, p_cnt);

    // MoE expert GEMMs (fp16; 2 CTAs/SM; gemm1 gathers A rows via etok)
    gemm_h_k<2, true, true, 128><<<dim3(FFNm / 128, CAPn / 128, En), 256, H_SMEM128>>>(
        p_xn2h, p_w1h, p_hh, FFNm, Dm, nullptr, p_cnt, p_etok,
        nullptr, nullptr, nullptr, nullptr,
        0, (long)Dm * FFNm, (long)CAPn * FFNm, 0);
    gemm_h_k<3, true, false, 128><<<dim3(Dm / 128, CAPn / 128, En), 256, H_SMEM128>>>(
        p_hh, p_w2h, p_ye, Dm, FFNm, p_egate, p_cnt, nullptr,
        nullptr, nullptr, nullptr, nullptr,
        (long)CAPn * FFNm, (long)FFNm * Dm, (long)CAPn * Dm, CAPn);

    // out = x1 + moe
    combine_k<<<Tn, 256>>>(p_x1, p_ye, p_fe, p_slot, out);
}

// round 16
// speedup vs baseline: 7.2917x; 1.0897x over previous
#include <cuda_runtime.h>
#include <cuda_fp16.h>
#include <math.h>
#include <stdint.h>

// ---------------------------------------------------------------------------
// Problem constants
// ---------------------------------------------------------------------------
namespace {
constexpr int Bz   = 2;
constexpr int Sq   = 2048;
constexpr int Dm   = 1024;
constexpr int Hn   = 16;
constexpr int HDm  = 64;
constexpr int FFNm = 2048;
constexpr int En   = 8;
constexpr int Tn   = Bz * Sq;     // 4096 tokens
constexpr int NA   = Tn * 2;      // 8192 flat assignments (top-2)
constexpr int CAPn = 1280;        // ceil(2*2048*2*1.25/8)
// prep_k region sizes (float4 units except rope)
constexpr int NQ4  = Dm * 3 * Dm / 4;        // 786432
constexpr int NO4  = Dm * Dm / 4;            // 262144
constexpr int NW14 = En * Dm * FFNm / 4;     // 4194304
constexpr int NW24 = En * FFNm * Dm / 4;     // 4194304
constexpr int NRP  = Sq * (HDm / 2);         // 65536
}

// ---------------------------------------------------------------------------
// Static scratch (no allocations allowed)
// ---------------------------------------------------------------------------
__device__ float g_x1  [Tn * Dm];
__device__ float g_cos [Sq * (HDm / 2)];
__device__ float g_sin [Sq * (HDm / 2)];
__device__ float g_fg  [NA];
__device__ int   g_fe  [NA];
__device__ int   g_slot[NA];
__device__ int   g_etok [En * CAPn];
__device__ float g_egate[En * CAPn];
__device__ int   g_cnt  [En];               // live rows per expert
__device__ float g_ye[En * CAPn * Dm];
// fp16 data
__device__ __half g_qh   [Tn * Dm];         // rope'd Q, pre-scaled 1/8
__device__ __half g_kh   [Tn * Dm];         // rope'd K
__device__ __half g_vh   [Tn * Dm];         // V
__device__ __half g_xnh  [Tn * Dm];         // rmsnorm1 out (qkv GEMM A)
__device__ __half g_xn2h [Tn * Dm];         // rmsnorm2 out (MoE gather src)
__device__ __half g_attnh[Tn * Dm];         // attention out (o GEMM A)
__device__ __half g_wqkvh[Dm * 3 * Dm];
__device__ __half g_woh  [Dm * Dm];
__device__ __half g_w1h  [En * Dm * FFNm];
__device__ __half g_w2h  [En * FFNm * Dm];
__device__ __half g_hh   [En * CAPn * FFNm];

// ---------------------------------------------------------------------------
// Helpers
// ---------------------------------------------------------------------------
__device__ __forceinline__ uint32_t smem_u32(const void* p) {
    uint32_t a;
    asm("{ .reg .u64 t; cvta.to.shared.u64 t, %1; cvt.u32.u64 %0, t; }"
        : "=r"(a) : "l"(p));
    return a;
}

__device__ __forceinline__ void cpasync16(uint32_t dst, const void* src) {
    asm volatile("cp.async.cg.shared.global [%0], [%1], 16;" :: "r"(dst), "l"(src));
}
// Zero-fill variant: src-size 0 -> smem dst gets zeros, no global read.
__device__ __forceinline__ void cpasync16z(uint32_t dst, const void* src, uint32_t ssz) {
    asm volatile("cp.async.cg.shared.global [%0], [%1], 16, %2;"
                 :: "r"(dst), "l"(src), "r"(ssz));
}
__device__ __forceinline__ void cp_commit() {
    asm volatile("cp.async.commit_group;" ::: "memory");
}
template <int N>
__device__ __forceinline__ void cp_wait() {
    asm volatile("cp.async.wait_group %0;" :: "n"(N) : "memory");
}

// fp16 m16n8k16 MMA, fp32 accumulate
__device__ __forceinline__ void mma_f16(float* d, const uint32_t* a, const uint32_t* b) {
    asm volatile(
        "mma.sync.aligned.m16n8k16.row.col.f32.f16.f16.f32 "
        "{%0,%1,%2,%3}, {%4,%5,%6,%7}, {%8,%9}, {%0,%1,%2,%3};"
        : "+f"(d[0]), "+f"(d[1]), "+f"(d[2]), "+f"(d[3])
        : "r"(a[0]), "r"(a[1]), "r"(a[2]), "r"(a[3]), "r"(b[0]), "r"(b[1]));
}

__device__ __forceinline__ void ldsm_x4(uint32_t* r, uint32_t addr) {
    asm volatile("ldmatrix.sync.aligned.m8n8.x4.shared.b16 {%0,%1,%2,%3}, [%4];"
                 : "=r"(r[0]), "=r"(r[1]), "=r"(r[2]), "=r"(r[3]) : "r"(addr));
}
__device__ __forceinline__ void ldsm_x4_t(uint32_t* r, uint32_t addr) {
    asm volatile("ldmatrix.sync.aligned.m8n8.x4.trans.shared.b16 {%0,%1,%2,%3}, [%4];"
                 : "=r"(r[0]), "=r"(r[1]), "=r"(r[2]), "=r"(r[3]) : "r"(addr));
}

// 2^x for x <= 0, FMA-pipe only. Degree-4 Taylor on [-0.5, 0.5]:
// truncation <= 4.2e-5 relative — below fp16 rounding of the consumer (P).
__device__ __forceinline__ float exp2p(float x) {
    float t = fmaxf(x, -126.f);
    float z = t + 12582912.f;
    float n = z - 12582912.f;
    float f = t - n;
    float p =         9.6181291e-3f;
    p = fmaf(p, f, 5.5504109e-2f);
    p = fmaf(p, f, 2.4022651e-1f);
    p = fmaf(p, f, 6.9314718e-1f);
    p = fmaf(p, f, 1.0f);
    int iz = __float_as_int(z) - 0x4B400000;
    return p * __int_as_float((iz + 127) << 23);
}

__device__ __forceinline__ uint32_t h2_bits(float a, float b) {
    __half2 h = __float22half2_rn(make_float2(a, b));
    return *(uint32_t*)&h;
}

// ---------------------------------------------------------------------------
// Fused prep: fp16-convert all four weight tensors + rope table. One launch.
// ---------------------------------------------------------------------------
__global__ void prep_k(const float* __restrict__ wqkv, __half* __restrict__ wqkvh,
                       const float* __restrict__ wo,   __half* __restrict__ woh,
                       const float* __restrict__ w1,   __half* __restrict__ w1h,
                       const float* __restrict__ w2,   __half* __restrict__ w2h,
                       float* __restrict__ ct, float* __restrict__ st) {
    const int total = NQ4 + NO4 + NW14 + NW24 + NRP;
    int stride = gridDim.x * blockDim.x;
    for (int i = blockIdx.x * blockDim.x + threadIdx.x; i < total; i += stride) {
        int r = i;
        if (r < NQ4) {
            float4 v = ((const float4*)wqkv)[r];
            ((uint2*)wqkvh)[r] = make_uint2(h2_bits(v.x, v.y), h2_bits(v.z, v.w));
            continue;
        }
        r -= NQ4;
        if (r < NO4) {
            float4 v = ((const float4*)wo)[r];
            ((uint2*)woh)[r] = make_uint2(h2_bits(v.x, v.y), h2_bits(v.z, v.w));
            continue;
        }
        r -= NO4;
        if (r < NW14) {
            float4 v = ((const float4*)w1)[r];
            ((uint2*)w1h)[r] = make_uint2(h2_bits(v.x, v.y), h2_bits(v.z, v.w));
            continue;
        }
        r -= NW14;
        if (r < NW24) {
            float4 v = ((const float4*)w2)[r];
            ((uint2*)w2h)[r] = make_uint2(h2_bits(v.x, v.y), h2_bits(v.z, v.w));
            continue;
        }
        r -= NW24;
        {
            int s = r >> 5, j = r & 31;
            float th = (float)pow(10000.0, -2.0 * (double)j / (double)HDm);
            double f = (double)s * (double)th;
            ct[r] = (float)cos(f);
            st[r] = (float)sin(f);
        }
    }
}

// ---------------------------------------------------------------------------
// RMSNorm (fp16 out; feeds qkv GEMM)
// ---------------------------------------------------------------------------
__global__ void __launch_bounds__(256) rmsnorm_k(const float* __restrict__ x,
                                                 const float* __restrict__ g,
                                                 __half* __restrict__ y) {
    int row = blockIdx.x;
    int i = threadIdx.x;
    const float4* xr = (const float4*)(x + (size_t)row * Dm);
    float4 xv = xr[i];
    float ss = xv.x * xv.x + xv.y * xv.y + xv.z * xv.z + xv.w * xv.w;
#pragma unroll
    for (int off = 16; off; off >>= 1) ss += __shfl_down_sync(0xffffffffu, ss, off);
    __shared__ float red[8];
    __shared__ float srms;
    if ((i & 31) == 0) red[i >> 5] = ss;
    __syncthreads();
    if (i == 0) {
        float t = 0.f;
#pragma unroll
        for (int w = 0; w < 8; w++) t += red[w];
        srms = rsqrtf(t * (1.0f / Dm) + 1e-6f);
    }
    __syncthreads();
    float r = srms;
    float4 gv = ((const float4*)g)[i];
    ((uint2*)(y + (size_t)row * Dm))[i] =
        make_uint2(h2_bits(gv.x * xv.x * r, gv.y * xv.y * r),
                   h2_bits(gv.z * xv.z * r, gv.w * xv.w * r));
}

// ---------------------------------------------------------------------------
// Fused RMSNorm2 + router: norm -> xn (fp16, MoE gather source), 8 logits,
// softmax, top-2. One block per token.
// ---------------------------------------------------------------------------
__global__ void __launch_bounds__(256) rmsrouter_k(const float* __restrict__ x,
                                                   const float* __restrict__ g,
                                                   const float* __restrict__ wr,
                                                   __half* __restrict__ xnh,
                                                   float* __restrict__ fg,
                                                   int* __restrict__ fe,
                                                   int* __restrict__ cnt) {
    int row = blockIdx.x;
    int i = threadIdx.x;
    if (row == 0 && i < En) cnt[i] = 0;
    const float4* xr = (const float4*)(x + (size_t)row * Dm);
    float4 xv = xr[i];
    float ss = xv.x * xv.x + xv.y * xv.y + xv.z * xv.z + xv.w * xv.w;
#pragma unroll
    for (int off = 16; off; off >>= 1) ss += __shfl_down_sync(0xffffffffu, ss, off);
    __shared__ float red[8];
    __shared__ float srms;
    if ((i & 31) == 0) red[i >> 5] = ss;
    __syncthreads();
    if (i == 0) {
        float t = 0.f;
#pragma unroll
        for (int w = 0; w < 8; w++) t += red[w];
        srms = rsqrtf(t * (1.0f / Dm) + 1e-6f);
    }
    __syncthreads();
    float r = srms;
    float4 gv = ((const float4*)g)[i];
    float o[4];
    o[0] = gv.x * xv.x * r; o[1] = gv.y * xv.y * r;
    o[2] = gv.z * xv.z * r; o[3] = gv.w * xv.w * r;
    ((uint2*)(xnh + (size_t)row * Dm))[i] =
        make_uint2(h2_bits(o[0], o[1]), h2_bits(o[2], o[3]));

    float acc[8];
#pragma unroll
    for (int e = 0; e < 8; e++) acc[e] = 0.f;
#pragma unroll
    for (int c = 0; c < 4; c++) {
        const float4* w = (const float4*)(wr + (size_t)(4 * i + c) * En);
        float4 w0 = w[0], w1 = w[1];
        acc[0] = fmaf(o[c], w0.x, acc[0]); acc[1] = fmaf(o[c], w0.y, acc[1]);
        acc[2] = fmaf(o[c], w0.z, acc[2]); acc[3] = fmaf(o[c], w0.w, acc[3]);
        acc[4] = fmaf(o[c], w1.x, acc[4]); acc[5] = fmaf(o[c], w1.y, acc[5]);
        acc[6] = fmaf(o[c], w1.z, acc[6]); acc[7] = fmaf(o[c], w1.w, acc[7]);
    }
#pragma unroll
    for (int e = 0; e < 8; e++)
#pragma unroll
        for (int off = 16; off; off >>= 1)
            acc[e] += __shfl_down_sync(0xffffffffu, acc[e], off);
    __shared__ float lred[8][8];
    if ((i & 31) == 0)
#pragma unroll
        for (int e = 0; e < 8; e++) lred[i >> 5][e] = acc[e];
    __syncthreads();
    if (i == 0) {
        float p[8];
#pragma unroll
        for (int e = 0; e < 8; e++) {
            float s = 0.f;
#pragma unroll
            for (int w = 0; w < 8; w++) s += lred[w][e];
            p[e] = s;
        }
        float mx = p[0];
#pragma unroll
        for (int e = 1; e < 8; e++) mx = fmaxf(mx, p[e]);
        float sum = 0.f;
#pragma unroll
        for (int e = 0; e < 8; e++) { p[e] = expf(p[e] - mx); sum += p[e]; }
        float inv = 1.f / sum;
#pragma unroll
        for (int e = 0; e < 8; e++) p[e] *= inv;
        int e0 = 0; float p0 = p[0];
#pragma unroll
        for (int e = 1; e < 8; e++) if (p[e] > p0) { p0 = p[e]; e0 = e; }
        int e1 = -1; float p1 = -1.f;
#pragma unroll
        for (int e = 0; e < 8; e++)
            if (e != e0 && p[e] > p1) { p1 = p[e]; e1 = e; }
        fg[2 * row]     = p0; fe[2 * row]     = e0;
        fg[2 * row + 1] = p1; fe[2 * row + 1] = e1;
    }
}

// ---------------------------------------------------------------------------
// Tensor-core causal flash attention, all-fp16 MMAs.
// K AND V both stored in 128B-row chunk-swizzled smem; both QK^T and PV
// fragments come from ldmatrix (QK non-trans, PV trans) — no scalar LDS in
// the mainloop. exp2 poly degree 4. 2 CTAs/SM; heavy diagonal CTAs first.
// ---------------------------------------------------------------------------
__global__ void __launch_bounds__(256, 2) attn_tc_k(const __half* __restrict__ Q,
                                                    const __half* __restrict__ Kt,
                                                    const __half* __restrict__ Vt,
                                                    __half* __restrict__ Out) {
    extern __shared__ __align__(16) char smc[];
    constexpr float LOG2E = 1.4426950408889634f;
    constexpr int KBYTES = 64 * 128;            // 8192
    constexpr int STGB = KBYTES + 64 * 128;     // 16384

    int bx = gridDim.x - 1 - blockIdx.x;        // heavy tiles first
    int h = blockIdx.y, b = blockIdx.z;
    int qt = bx * 128;
    int tid = threadIdx.x, warp = tid >> 5, lane = tid & 31;
    int gq = lane >> 2, tq = lane & 3;
    int wq = qt + warp * 16;
    const size_t base = ((size_t)(b * Hn + h)) * Sq * HDm;
    const __half* Qg = Q + base;
    const __half* Kg = Kt + base;
    const __half* Vg = Vt + base;

    const uint32_t sb = smem_u32(smc);

    uint32_t qf[4][4];
#pragma unroll
    for (int kk = 0; kk < 4; kk++) {
        const __half* q0 = Qg + (size_t)(wq + gq) * 64 + kk * 16 + 2 * tq;
        const __half* q1 = Qg + (size_t)(wq + gq + 8) * 64 + kk * 16 + 2 * tq;
        qf[kk][0] = *(const uint32_t*)q0;
        qf[kk][1] = *(const uint32_t*)q1;
        qf[kk][2] = *(const uint32_t*)(q0 + 8);
        qf[kk][3] = *(const uint32_t*)(q1 + 8);
    }

    float O[8][4];
#pragma unroll
    for (int nt = 0; nt < 8; nt++)
#pragma unroll
        for (int c = 0; c < 4; c++) O[nt][c] = 0.f;
    float m0 = -1e30f, m1 = -1e30f, l0 = 0.f, l1 = 0.f;

    int fr = tid >> 2;
    int fc = tid & 3;
    auto fill = [&](int stage, int kt) {
        // K and V: identical 128B-row chunk-swizzled layout, 2 chunks/thread each
        uint32_t kBase = sb + (uint32_t)(stage * STGB + fr * 128);
        uint32_t vBase = kBase + (uint32_t)KBYTES;
        const __half* ks = Kg + (size_t)(kt + fr) * 64;
        const __half* vs = Vg + (size_t)(kt + fr) * 64;
        uint32_t sw = (uint32_t)(fr & 7);
#pragma unroll
        for (int j = 0; j < 2; j++) {
            uint32_t c = (uint32_t)(fc * 2 + j);
            cpasync16(kBase + ((c ^ sw) * 16u), ks + c * 8);
            cpasync16(vBase + ((c ^ sw) * 16u), vs + c * 8);
        }
    };

    int ntiles = 2 * bx + 2;
    fill(0, 0);
    cp_commit();

    int lrow = lane & 7, selb = (lane >> 3) & 1, selc = lane >> 4;

    for (int it = 0; it < ntiles; it++) {
        if (it + 1 < ntiles) fill((it + 1) & 1, (it + 1) * 64);
        cp_commit();
        cp_wait<1>();
        __syncthreads();

        int kt = it * 64;
        if (kt <= wq + 15) {
            const uint32_t Ksb = sb + (uint32_t)((it & 1) * STGB);
            const uint32_t Vsb = Ksb + (uint32_t)KBYTES;

            // ---- S = Q K^T (fp16 MMA; K frags via non-trans ldmatrix) ----
            // matrix m = lane>>3: m0/m1 -> key-group lo (c lo/hi),
            //                     m2/m3 -> key-group hi (c lo/hi)
            float s[8][4];
#pragma unroll
            for (int nt = 0; nt < 8; nt++)
#pragma unroll
                for (int c = 0; c < 4; c++) s[nt][c] = 0.f;
#pragma unroll
            for (int kk = 0; kk < 4; kk++) {
                uint32_t bf[8][2];
#pragma unroll
                for (int t2 = 0; t2 < 4; t2++) {
                    uint32_t qd[4];
                    uint32_t key = (uint32_t)(t2 * 16 + 8 * selc + lrow);
                    uint32_t c = (uint32_t)(kk * 2 + selb);
                    uint32_t addr = Ksb + key * 128u + ((c ^ (uint32_t)lrow) * 16u);
                    ldsm_x4(qd, addr);
                    bf[2 * t2][0]     = qd[0]; bf[2 * t2][1]     = qd[1];
                    bf[2 * t2 + 1][0] = qd[2]; bf[2 * t2 + 1][1] = qd[3];
                }
#pragma unroll
                for (int nt = 0; nt < 8; nt++) mma_f16(s[nt], qf[kk], bf[nt]);
            }

            if (kt + 63 > wq) {
                int r0 = wq + gq, r1 = wq + gq + 8;
#pragma unroll
                for (int nt = 0; nt < 8; nt++) {
                    int c0 = kt + nt * 8 + 2 * tq;
                    if (c0 > r0)     s[nt][0] = -3.4e38f;
                    if (c0 + 1 > r0) s[nt][1] = -3.4e38f;
                    if (c0 > r1)     s[nt][2] = -3.4e38f;
                    if (c0 + 1 > r1) s[nt][3] = -3.4e38f;
                }
            }

            float mx0 = -3.4e38f, mx1 = -3.4e38f;
#pragma unroll
            for (int nt = 0; nt < 8; nt++) {
                mx0 = fmaxf(mx0, fmaxf(s[nt][0], s[nt][1]));
                mx1 = fmaxf(mx1, fmaxf(s[nt][2], s[nt][3]));
            }
            mx0 = fmaxf(mx0, __shfl_xor_sync(0xffffffffu, mx0, 1));
            mx0 = fmaxf(mx0, __shfl_xor_sync(0xffffffffu, mx0, 2));
            mx1 = fmaxf(mx1, __shfl_xor_sync(0xffffffffu, mx1, 1));
            mx1 = fmaxf(mx1, __shfl_xor_sync(0xffffffffu, mx1, 2));
            float mn0 = fmaxf(m0, mx0), mn1 = fmaxf(m1, mx1);
            float cr0 = exp2p((m0 - mn0) * LOG2E);
            float cr1 = exp2p((m1 - mn1) * LOG2E);
            float nm0 = mn0 * LOG2E, nm1 = mn1 * LOG2E;

            float sum0 = 0.f, sum1 = 0.f;
#pragma unroll
            for (int nt = 0; nt < 8; nt++) {
                float p0 = exp2p(fmaf(s[nt][0], LOG2E, -nm0));
                float p1 = exp2p(fmaf(s[nt][1], LOG2E, -nm0));
                float p2 = exp2p(fmaf(s[nt][2], LOG2E, -nm1));
                float p3 = exp2p(fmaf(s[nt][3], LOG2E, -nm1));
                s[nt][0] = p0; s[nt][1] = p1; s[nt][2] = p2; s[nt][3] = p3;
                sum0 += p0 + p1; sum1 += p2 + p3;
            }
            sum0 += __shfl_xor_sync(0xffffffffu, sum0, 1);
            sum0 += __shfl_xor_sync(0xffffffffu, sum0, 2);
            sum1 += __shfl_xor_sync(0xffffffffu, sum1, 1);
            sum1 += __shfl_xor_sync(0xffffffffu, sum1, 2);
            l0 = l0 * cr0 + sum0;
            l1 = l1 * cr1 + sum1;
#pragma unroll
            for (int nt = 0; nt < 8; nt++) {
                O[nt][0] *= cr0; O[nt][1] *= cr0;
                O[nt][2] *= cr1; O[nt][3] *= cr1;
            }
            m0 = mn0; m1 = mn1;

            // ---- O += P V (fp16 MMA; C frag -> A frag direct, no shfl) ----
#pragma unroll
            for (int kk = 0; kk < 4; kk++) {
                uint32_t a[4];
                a[0] = h2_bits(s[2 * kk][0],     s[2 * kk][1]);
                a[1] = h2_bits(s[2 * kk][2],     s[2 * kk][3]);
                a[2] = h2_bits(s[2 * kk + 1][0], s[2 * kk + 1][1]);
                a[3] = h2_bits(s[2 * kk + 1][2], s[2 * kk + 1][3]);
                uint32_t bvv[8][2];
#pragma unroll
                for (int np = 0; np < 4; np++) {
                    uint32_t qd[4];
                    uint32_t addr = Vsb + (uint32_t)((lrow + 8 * selb) * 128)
                                  + (uint32_t)(kk * 2048)
                                  + ((((uint32_t)(selc + 2 * np)) ^ (uint32_t)lrow) * 16u);
                    ldsm_x4_t(qd, addr);
                    bvv[2 * np][0]     = qd[0]; bvv[2 * np][1]     = qd[1];
                    bvv[2 * np + 1][0] = qd[2]; bvv[2 * np + 1][1] = qd[3];
                }
#pragma unroll
                for (int nt = 0; nt < 8; nt++) mma_f16(O[nt], a, bvv[nt]);
            }
        }
        __syncthreads();
    }

    float i0 = 1.f / l0, i1 = 1.f / l1;
    int r0 = wq + gq, r1 = wq + gq + 8;
    __half* o0 = Out + ((size_t)(b * Sq + r0)) * Dm + h * 64 + 2 * tq;
    __half* o1 = Out + ((size_t)(b * Sq + r1)) * Dm + h * 64 + 2 * tq;
#pragma unroll
    for (int nt = 0; nt < 8; nt++) {
        *(uint32_t*)(o0 + nt * 8) = h2_bits(O[nt][0] * i0, O[nt][1] * i0);
        *(uint32_t*)(o1 + nt * 8) = h2_bits(O[nt][2] * i1, O[nt][3] * i1);
    }
}

// ---------------------------------------------------------------------------
// fp16 tensor-core GEMM: CTA 128xNT, 8 warps, BK=32, 4-stage cp.async,
// ldmatrix, m16n8k16.f16, ONE barrier/iter. NT=128 kernels run 2 CTAs/SM.
// MODE 0: C(f32)=A@B            1: +resid
// MODE 2: C(f16)=relu(A@B)      3: C(f32)=(A@B)*gates[row]
// MODE 4: rope+split epilogue -> q(x1/8)/k/v fp16 (qkv projection)
// SKIP: early-exit CTAs past cnt[e]. GATHER: A rows via etok (zero-fill dead).
// ---------------------------------------------------------------------------
template <int MODE, bool SKIP, bool GATHER, int NT>
__global__ void __launch_bounds__(256, (NT == 128) ? 2 : 1)
gemm_h_k(const __half* __restrict__ A, const __half* __restrict__ Bm,
         void* __restrict__ Cp, int N, int K,
         const float* __restrict__ extra, const int* __restrict__ cnt,
         const int* __restrict__ etok,
         const float* __restrict__ ct, const float* __restrict__ st,
         __half* __restrict__ kOut, __half* __restrict__ vOut,
         long sA, long sB, long sC, int gstride) {
    extern __shared__ __align__(16) float smf[];
    const uint32_t sb = smem_u32(smf);
    constexpr int NTW  = NT / 32;
    constexpr int CPT  = NT / 64;
    constexpr uint32_t BROW = NT * 2;
    constexpr uint32_t STGB = 8192u + 32u * BROW;

    int e = blockIdx.z;
    int m0 = blockIdx.y * 128, n0 = blockIdx.x * NT;
    int cntE = 0;
    if (SKIP) {
        cntE = cnt[e];
        if (m0 >= cntE) return;
    }

    int tid = threadIdx.x, warp = tid >> 5, lane = tid & 31;
    int gq = lane >> 2, tq = lane & 3;
    if (!GATHER) A += (size_t)e * sA;
    Bm += (size_t)e * sB;
    const float* gates = extra;
    if (MODE == 3) gates += (size_t)e * gstride;

    int wm = (warp & 1) * 64, wn = (warp >> 1) * (NT / 4);

    int ar = tid >> 1, ah = tid & 1;
    int br2 = tid >> 3, bc0 = (tid & 7) * CPT;
    const __half* aSrc;
    uint32_t aLive = 16u;
    if (GATHER) {
        int rr = m0 + ar;
        bool live = rr < cntE;
        int tok = live ? etok[e * CAPn + rr] : 0;
        aLive = live ? 16u : 0u;
        aSrc = A + (size_t)tok * K + ah * 16;
    } else {
        aSrc = A + (size_t)(m0 + ar) * K + ah * 16;
    }
    const __half* bSrc = Bm + (size_t)br2 * N + n0 + bc0 * 8;
    uint32_t aS = (ar >> 1) & 3;
    uint32_t aBase = sb + (uint32_t)ar * 64u;
    uint32_t bBase = sb + 8192u + (uint32_t)br2 * BROW;

    auto fetch = [&](int stage, int k0) {
        uint32_t so = (uint32_t)stage * STGB;
        const __half* as = aSrc + k0;
        uint32_t c0 = 2u * ah;
        if (GATHER) {
            cpasync16z(aBase + so + ((c0 ^ aS) * 16u), as, aLive);
            cpasync16z(aBase + so + (((c0 + 1) ^ aS) * 16u), as + 8, aLive);
        } else {
            cpasync16(aBase + so + ((c0 ^ aS) * 16u), as);
            cpasync16(aBase + so + (((c0 + 1) ^ aS) * 16u), as + 8);
        }
        const __half* bs = bSrc + (size_t)k0 * N;
#pragma unroll
        for (int j = 0; j < CPT; j++) {
            uint32_t c = (uint32_t)(bc0 + j);
            cpasync16(bBase + so + ((c ^ (uint32_t)(br2 & 7)) * 16u), bs + j * 8);
        }
    };

    float d[4][NTW][4];
#pragma unroll
    for (int i = 0; i < 4; i++)
#pragma unroll
        for (int j = 0; j < NTW; j++)
#pragma unroll
            for (int c = 0; c < 4; c++) d[i][j][c] = 0.f;

    fetch(0, 0);  cp_commit();
    fetch(1, 32); cp_commit();
    fetch(2, 64); cp_commit();

    int lrow = lane & 7, selb = (lane >> 3) & 1, selc = lane >> 4;
    uint32_t aRow = (uint32_t)(wm + lrow + 8 * selb) * 64u;
    uint32_t aSw  = (uint32_t)((lrow >> 1) & 3);
    uint32_t bRow = (uint32_t)(lrow + 8 * selb) * BROW;
    uint32_t bCb  = (uint32_t)((wn >> 3) + selc);

    int KB = K >> 5;
    for (int it = 0; it < KB; ++it) {
        cp_wait<2>();
        __syncthreads();
        if (it + 3 < KB) fetch((it + 3) & 3, (it + 3) * 32);
        cp_commit();

        uint32_t As = sb + (uint32_t)(it & 3) * STGB;
        uint32_t Bs = As + 8192u;
#pragma unroll
        for (int kk = 0; kk < 2; kk++) {
            uint32_t a[4][4], b[NTW][2];
#pragma unroll
            for (int mt = 0; mt < 4; mt++) {
                uint32_t addr = As + aRow + (uint32_t)mt * 1024u
                              + ((((uint32_t)(2 * kk) + (uint32_t)selc) ^ aSw) * 16u);
                ldsm_x4(a[mt], addr);
            }
#pragma unroll
            for (int np = 0; np < NTW / 2; np++) {
                uint32_t q[4];
                uint32_t addr = Bs + bRow + (uint32_t)kk * 16u * BROW
                              + (((bCb + 2u * np) ^ (uint32_t)lrow) * 16u);
                ldsm_x4_t(q, addr);
                b[2 * np][0]     = q[0]; b[2 * np][1]     = q[1];
                b[2 * np + 1][0] = q[2]; b[2 * np + 1][1] = q[3];
            }
#pragma unroll
            for (int mt = 0; mt < 4; mt++)
#pragma unroll
                for (int nt = 0; nt < NTW; nt++)
                    mma_f16(d[mt][nt], a[mt], b[nt]);
        }
    }

    if (MODE == 4) {
        int region = n0 >> 10;
        __half* q0v[3] = { (__half*)Cp, kOut, vOut };
        __half* outb = q0v[region];
#pragma unroll
        for (int mt = 0; mt < 4; mt++) {
#pragma unroll
            for (int half = 0; half < 2; half++) {
                int row = m0 + wm + mt * 16 + gq + 8 * half;
                int bb = row >> 11, s = row & (Sq - 1);
                float va = 0.f, vb = 0.f;
#pragma unroll
                for (int nt = 0; nt < NTW; nt++) {
                    int c = n0 + wn + nt * 8 + 2 * tq;
                    va = d[mt][nt][2 * half];
                    vb = d[mt][nt][2 * half + 1];
                    int cc = c & 1023;
                    int hh = cc >> 6, dd = cc & 63;
                    size_t off = ((size_t)(bb * Hn + hh) * Sq + s) * HDm + dd;
                    uint32_t bits;
                    if (region == 2) {
                        bits = h2_bits(va, vb);
                    } else {
                        int j = dd >> 1;
                        float cs = ct[s * 32 + j], sn = st[s * 32 + j];
                        float orr = va * cs - vb * sn;
                        float oii = va * sn + vb * cs;
                        if (region == 0) { orr *= 0.125f; oii *= 0.125f; }
                        bits = h2_bits(orr, oii);
                    }
                    *(uint32_t*)(outb + off) = bits;
                }
            }
        }
        return;
    }

#pragma unroll
    for (int mt = 0; mt < 4; mt++) {
        int r0 = m0 + wm + mt * 16 + gq;
        int r1 = r0 + 8;
        if (MODE == 2) {
            __half* Cb = (__half*)Cp + (size_t)e * sC;
#pragma unroll
            for (int nt = 0; nt < NTW; nt++) {
                int c = n0 + wn + nt * 8 + 2 * tq;
                *(uint32_t*)(Cb + (size_t)r0 * N + c) =
                    h2_bits(fmaxf(d[mt][nt][0], 0.f), fmaxf(d[mt][nt][1], 0.f));
                *(uint32_t*)(Cb + (size_t)r1 * N + c) =
                    h2_bits(fmaxf(d[mt][nt][2], 0.f), fmaxf(d[mt][nt][3], 0.f));
            }
        } else if (MODE != 4) {
            float* Cf = (float*)Cp + (size_t)e * sC;
            float g0 = 1.f, g1 = 1.f;
            if (MODE == 3) { g0 = gates[r0]; g1 = gates[r1]; }
#pragma unroll
            for (int nt = 0; nt < NTW; nt++) {
                int c = n0 + wn + nt * 8 + 2 * tq;
                float2 u, w;
                u.x = d[mt][nt][0]; u.y = d[mt][nt][1];
                w.x = d[mt][nt][2]; w.y = d[mt][nt][3];
                if (MODE == 1) {
                    float2 ra = *(const float2*)(extra + (size_t)r0 * N + c);
                    float2 rb = *(const float2*)(extra + (size_t)r1 * N + c);
                    u.x += ra.x; u.y += ra.y;
                    w.x += rb.x; w.y += rb.y;
                }
                if (MODE == 3) {
                    u.x *= g0; u.y *= g0;
                    w.x *= g1; w.y *= g1;
                }
                *(float2*)(Cf + (size_t)r0 * N + c) = u;
                *(float2*)(Cf + (size_t)r1 * N + c) = w;
            }
        }
    }
}

// ---------------------------------------------------------------------------
// Exact capacity ranking (j-loop vectorized x4).
// ---------------------------------------------------------------------------
__global__ void __launch_bounds__(256) rank_k(const float* __restrict__ fg,
                                              const int* __restrict__ fe,
                                              int* __restrict__ slot,
                                              int* __restrict__ etok,
                                              float* __restrict__ egate,
                                              int* __restrict__ cnt) {
    __shared__ float sg[NA];
    __shared__ unsigned char se[NA];
    for (int i = threadIdx.x; i < NA; i += 256) {
        sg[i] = fg[i];
        se[i] = (unsigned char)fe[i];
    }
    __syncthreads();
    int i = blockIdx.x * 256 + threadIdx.x;
    float gi = sg[i];
    unsigned char ei = se[i];
    int r = 0;
    const float4* sg4 = (const float4*)sg;
    const uchar4* se4 = (const uchar4*)se;
    for (int j4 = 0; j4 < NA / 4; j4++) {
        float4 g4 = sg4[j4];
        uchar4 e4 = se4[j4];
        int j = 4 * j4;
        r += (int)((e4.x == ei) && ((g4.x > gi) || (g4.x == gi && (j + 0) < i)));
        r += (int)((e4.y == ei) && ((g4.y > gi) || (g4.y == gi && (j + 1) < i)));
        r += (int)((e4.z == ei) && ((g4.z > gi) || (g4.z == gi && (j + 2) < i)));
        r += (int)((e4.w == ei) && ((g4.w > gi) || (g4.w == gi && (j + 3) < i)));
    }
    if (r < CAPn) {
        slot[i] = r;
        etok[(int)ei * CAPn + r] = i >> 1;
        egate[(int)ei * CAPn + r] = gi;
        atomicMax(&cnt[(int)ei], r + 1);
    } else {
        slot[i] = -1;
    }
}

// ---------------------------------------------------------------------------
// Final combine
// ---------------------------------------------------------------------------
__global__ void __launch_bounds__(256) combine_k(const float* __restrict__ x1,
                                                 const float* __restrict__ ye,
                                                 const int* __restrict__ fe,
                                                 const int* __restrict__ slot,
                                                 float* __restrict__ out) {
    int t = blockIdx.x;
    int d = threadIdx.x;
    float4 v = ((const float4*)(x1 + (size_t)t * Dm))[d];
#pragma unroll
    for (int kk = 0; kk < 2; kk++) {
        int i = 2 * t + kk;
        int sl = slot[i];
        if (sl >= 0) {
            int e = fe[i];
            float4 w = ((const float4*)(ye + ((size_t)e * CAPn + sl) * Dm))[d];
            v.x += w.x; v.y += w.y; v.z += w.z; v.w += w.w;
        }
    }
    ((float4*)(out + (size_t)t * Dm))[d] = v;
}

// ---------------------------------------------------------------------------
// Launch (single stream)
// ---------------------------------------------------------------------------
extern "C" void kernel_launch(void* const* d_in, const int* in_sizes, int n_in,
                              void* d_out, int out_size) {
    (void)in_sizes; (void)n_in; (void)out_size;
    const float* x        = (const float*)d_in[0];
    const float* g1       = (const float*)d_in[1];
    const float* w_qkv    = (const float*)d_in[2];
    const float* w_o      = (const float*)d_in[3];
    const float* g2       = (const float*)d_in[4];
    const float* w_router = (const float*)d_in[5];
    const float* w1       = (const float*)d_in[6];
    const float* w2       = (const float*)d_in[7];
    float* out = (float*)d_out;

    float *p_x1, *p_cos, *p_sin, *p_fg, *p_egate, *p_ye;
    __half *p_qh, *p_kh, *p_vh, *p_xnh, *p_xn2h, *p_attnh;
    __half *p_wqkvh, *p_woh, *p_w1h, *p_w2h, *p_hh;
    int *p_fe, *p_slot, *p_etok, *p_cnt;
    cudaGetSymbolAddress((void**)&p_x1,    g_x1);
    cudaGetSymbolAddress((void**)&p_cos,   g_cos);
    cudaGetSymbolAddress((void**)&p_sin,   g_sin);
    cudaGetSymbolAddress((void**)&p_fg,    g_fg);
    cudaGetSymbolAddress((void**)&p_fe,    g_fe);
    cudaGetSymbolAddress((void**)&p_slot,  g_slot);
    cudaGetSymbolAddress((void**)&p_etok,  g_etok);
    cudaGetSymbolAddress((void**)&p_egate, g_egate);
    cudaGetSymbolAddress((void**)&p_cnt,   g_cnt);
    cudaGetSymbolAddress((void**)&p_ye,    g_ye);
    cudaGetSymbolAddress((void**)&p_qh,    g_qh);
    cudaGetSymbolAddress((void**)&p_kh,    g_kh);
    cudaGetSymbolAddress((void**)&p_vh,    g_vh);
    cudaGetSymbolAddress((void**)&p_xnh,   g_xnh);
    cudaGetSymbolAddress((void**)&p_xn2h,  g_xn2h);
    cudaGetSymbolAddress((void**)&p_attnh, g_attnh);
    cudaGetSymbolAddress((void**)&p_wqkvh, g_wqkvh);
    cudaGetSymbolAddress((void**)&p_woh,   g_woh);
    cudaGetSymbolAddress((void**)&p_w1h,   g_w1h);
    cudaGetSymbolAddress((void**)&p_w2h,   g_w2h);
    cudaGetSymbolAddress((void**)&p_hh,    g_hh);

    constexpr int H_SMEM256 = 4 * 24576;        // 98304 bytes
    constexpr int H_SMEM128 = 4 * 16384;        // 65536 bytes
    constexpr int ATTN_SMEM = 2 * 16384;        // 32768 bytes
    cudaFuncSetAttribute((const void*)gemm_h_k<4, false, false, 256>,
                         cudaFuncAttributeMaxDynamicSharedMemorySize, H_SMEM256);
    cudaFuncSetAttribute((const void*)gemm_h_k<1, false, false, 256>,
                         cudaFuncAttributeMaxDynamicSharedMemorySize, H_SMEM256);
    cudaFuncSetAttribute((const void*)gemm_h_k<2, true, true, 128>,
                         cudaFuncAttributeMaxDynamicSharedMemorySize, H_SMEM128);
    cudaFuncSetAttribute((const void*)gemm_h_k<3, true, false, 128>,
                         cudaFuncAttributeMaxDynamicSharedMemorySize, H_SMEM128);
    cudaFuncSetAttribute((const void*)attn_tc_k,
                         cudaFuncAttributeMaxDynamicSharedMemorySize, ATTN_SMEM);

    // Fused precompute: fp16 weight conversions + rope table in ONE launch
    prep_k<<<1184, 256>>>(w_qkv, p_wqkvh, w_o, p_woh,
                          w1, p_w1h, w2, p_w2h, p_cos, p_sin);

    // Attention branch: qkv GEMM with fused rope/split epilogue
    rmsnorm_k<<<Tn, 256>>>(x, g1, p_xnh);
    gemm_h_k<4, false, false, 256><<<dim3(3 * Dm / 256, Tn / 128, 1), 256, H_SMEM256>>>(
        p_xnh, p_wqkvh, p_qh, 3 * Dm, Dm, nullptr, nullptr, nullptr,
        p_cos, p_sin, p_kh, p_vh, 0, 0, 0, 0);
    attn_tc_k<<<dim3(Sq / 128, Hn, Bz), 256, ATTN_SMEM>>>(p_qh, p_kh, p_vh, p_attnh);
    gemm_h_k<1, false, false, 256><<<dim3(Dm / 256, Tn / 128, 1), 256, H_SMEM256>>>(
        p_attnh, p_woh, p_x1, Dm, Dm, x, nullptr, nullptr,
        nullptr, nullptr, nullptr, nullptr, 0, 0, 0, 0);

    // Fused rmsnorm2 + routing (fp32 exact; xn emitted fp16 for MoE gather)
    rmsrouter_k<<<Tn, 256>>>(p_x1, g2, w_router, p_xn2h, p_fg, p_fe, p_cnt);
    rank_k<<<NA / 256, 256>>>(p_fg, p_fe, p_slot, p_etok, p_egate, p_cnt);

    // MoE expert GEMMs (fp16; 2 CTAs/SM; gemm1 gathers A rows via etok)
    gemm_h_k<2, true, true, 128><<<dim3(FFNm / 128, CAPn / 128, En), 256, H_SMEM128>>>(
        p_xn2h, p_w1h, p_hh, FFNm, Dm, nullptr, p_cnt, p_etok,
        nullptr, nullptr, nullptr, nullptr,
        0, (long)Dm * FFNm, (long)CAPn * FFNm, 0);
    gemm_h_k<3, true, false, 128><<<dim3(Dm / 128, CAPn / 128, En), 256, H_SMEM128>>>(
        p_hh, p_w2h, p_ye, Dm, FFNm, p_egate, p_cnt, nullptr,
        nullptr, nullptr, nullptr, nullptr,
        (long)CAPn * FFNm, (long)FFNm * Dm, (long)CAPn * Dm, CAPn);

    // out = x1 + moe
    combine_k<<<Tn, 256>>>(p_x1, p_ye, p_fe, p_slot, out);
}